// round 8
// baseline (speedup 1.0000x reference)
#include <cuda_runtime.h>

#define BATCH 128
#define NT 512
#define NPACK 16          // pack blocks
#define TBS 1024          // TB row stride

__device__ float g_TB[51 * TBS];   // packed basis, transposed: TB[c][i]
__device__ float g_partials[BATCH];
__device__ unsigned int g_count = 0;
__device__ unsigned int g_pack = 0;

__device__ __forceinline__ float warp_sum(float v) {
#pragma unroll
    for (int o = 16; o; o >>= 1) v += __shfl_down_sync(0xffffffffu, v, o);
    return v;
}

// grid = 144. Blocks 0..127: batch. Blocks 128..143: pack 996 basis rows into g_TB.
__global__ __launch_bounds__(NT, 1)
void loss_main(const float* __restrict__ input,
               const float* __restrict__ target,
               const float* __restrict__ normals,
               const float* __restrict__ param_mean,
               const float* __restrict__ param_std,
               const float* __restrict__ u,
               const float* __restrict__ w_shp,
               const float* __restrict__ w_exp,
               const int*   __restrict__ keyindex,
               const int*   __restrict__ ridx_w,
               const int*   __restrict__ ridx_v,
               float* __restrict__ out)
{
    const int tid  = threadIdx.x;
    const int lane = tid & 31;
    const int wid  = tid >> 5;

    // ================= pack blocks =================
    // TB row i: [0,204) keypoint rows | [204,600) ridx_w rows | [600,996) ridx_v rows.
    // Col 0 = u; cols 1..40 = w_shp; cols 41..50 = w_exp.
    if (blockIdx.x >= BATCH) {
        const int p  = blockIdx.x - BATCH;
        const int i0 = p * 64;
        __shared__ float sm[64][53];
        for (int e = tid; e < 64 * 51; e += NT) {
            int rowk = e / 51, c = e % 51;
            int i = i0 + rowk;
            float v = 0.f;
            if (i < 996) {
                int j, cc, vid;
                if (i < 204)      { j = i / 3; cc = i % 3; vid = keyindex[j]; }
                else if (i < 600) { j = i / 3; cc = i % 3; vid = ridx_w[j - 68]; }
                else              { int m = i - 396; j = m / 3; cc = m % 3; vid = ridx_v[j - 68]; }
                size_t r = 3 * (size_t)vid + cc;
                v = (c == 0) ? u[r] : (c <= 40 ? w_shp[r * 40 + (c - 1)]
                                               : w_exp[r * 10 + (c - 41)]);
            }
            sm[rowk][c] = v;
        }
        __syncthreads();
        // transposed write: for fixed c, consecutive threads write consecutive i (coalesced)
        for (int e = tid; e < 51 * 64; e += NT) {
            int c = e / 64, rowk = e % 64;
            g_TB[c * TBS + i0 + rowk] = sm[rowk][c];
        }
        __threadfence();
        __syncthreads();
        if (tid == 0) atomicAdd(&g_pack, 1u);
        return;
    }

    // ================= batch blocks =================
    const int n = blockIdx.x;

    __shared__ float sp[62], spg[62];
    __shared__ float bv[600], bvg[600];
    __shared__ float tn_w[16][3];
    __shared__ float swcolsq[4][50];
    __shared__ float4 vt4[200], vtg4[200];
    __shared__ float wsum[16];
    __shared__ int   s_last;

    // ---- 0. params; warp 15: normals column sums (DRAM, overlaps pack wait); tid0 spins ----
    if (tid < 62) {
        float st = param_std[tid], mn = param_mean[tid];
        sp[tid]  = input [n * 62 + tid] * st + mn;
        spg[tid] = target[n * 62 + tid] * st + mn;
    }
    float ns0 = 0.f, ns1 = 0.f, ns2 = 0.f;
    if (wid == 15) {
        const float* nb = normals + (size_t)n * (68 * 68);
#pragma unroll 4
        for (int i = 0; i < 68; i++) {
            const float* rowp = nb + i * 68;
            ns0 += rowp[lane];
            ns1 += rowp[lane + 32];
            if (lane < 4) ns2 += rowp[lane + 64];
        }
    }
    if (tid == 0) {
        while (atomicAdd(&g_pack, 0u) < NPACK) __nanosleep(32);
    }
    __syncthreads();
    __threadfence();   // acquire g_TB

    // ---- 1. job loop: 996 basis-dot jobs + 200 wcol quarter-column jobs ----
    float tn0 = 0.f, tn1 = 0.f, tn2 = 0.f;
#pragma unroll 1
    for (int l = tid; l < 1196; l += NT) {
        if (l < 996) {
            const float* tb = g_TB + l;    // column c at tb[c*TBS]
            float u0 = tb[0];
            if (l < 204 || l >= 600) {
                // pred + gt
                float pa = u0, pb = 0.f, ga = u0, gb = 0.f;
#pragma unroll
                for (int c = 1; c <= 49; c += 2) {
                    float va = tb[c * TBS], vb = tb[(c + 1) * TBS];
                    pa += va * sp [11 + c];
                    pb += vb * sp [12 + c];
                    ga += va * spg[11 + c];
                    gb += vb * spg[12 + c];
                }
                float s = pa + pb, g = ga + gb;
                int d = (l < 204) ? l : l - 396;
                bv[d] = s; bvg[d] = g;
                if (l < 204) {
                    float s2 = s * s;
                    int c3 = l % 3;
                    if (c3 == 0) tn0 += s2; else if (c3 == 1) tn1 += s2; else tn2 += s2;
                }
            } else {
                // pred only (ridx_w rows) -> tn
                float pa = u0, pb = 0.f;
#pragma unroll
                for (int c = 1; c <= 49; c += 2) {
                    pa += tb[c * TBS] * sp[11 + c];
                    pb += tb[(c + 1) * TBS] * sp[12 + c];
                }
                float s = pa + pb;
                float s2 = s * s;
                int c3 = l % 3;
                if (c3 == 0) tn0 += s2; else if (c3 == 1) tn1 += s2; else tn2 += s2;
            }
        } else {
            // wcol quarter-column: col c over TB rows [h*150, h*150+150)
            int idx = l - 996;
            int c = idx % 50, h = idx / 50;
            const float2* b2 = (const float2*)(g_TB + (size_t)(c + 1) * TBS + h * 150);
            float a0 = 0.f, a1 = 0.f;
#pragma unroll 5
            for (int k = 0; k < 75; k += 2) {   // wait: 75 float2 = 150 floats; step 2 over [0,75)
                float2 x = b2[k];
                a0 += x.x * x.x + x.y * x.y;
                if (k + 1 < 75) {
                    float2 y = b2[k + 1];
                    a1 += y.x * y.x + y.y * y.y;
                }
            }
            swcolsq[h][c] = a0 + a1;
        }
    }
    tn0 = warp_sum(tn0); tn1 = warp_sum(tn1); tn2 = warp_sum(tn2);
    if (lane == 0) { tn_w[wid][0] = tn0; tn_w[wid][1] = tn1; tn_w[wid][2] = tn2; }
    __syncthreads();

    // ---- 2. warp 0: weights + wpdc; tid 64..263: rotate verts ----
    float tot = 0.f;
    if (wid == 0) {
        int p1 = lane, p2 = lane + 32;
        float wj1, wj2 = 0.f;
        {
            float pd = fabsf(sp[p1] - spg[p1]);
            if (p1 < 11) {
                int cc = p1 & 3;
                float sc;
                if (cc < 3) {
                    float t = 0.f;
#pragma unroll
                    for (int w = 0; w < 16; w++) t += tn_w[w][cc];
                    sc = sqrtf(t);
                } else sc = 14.142135623730951f;  // sqrt(200)
                wj1 = pd * sc + 1e-6f;
            } else if (p1 == 11) wj1 = 1e-6f;
            else {
                float cs = swcolsq[0][p1-12] + swcolsq[1][p1-12] + swcolsq[2][p1-12] + swcolsq[3][p1-12];
                wj1 = 0.00057339936f * pd * sqrtf(cs) + 1e-6f;
            }
        }
        if (p2 < 62) {
            float pd = fabsf(sp[p2] - spg[p2]);
            float cs = swcolsq[0][p2-12] + swcolsq[1][p2-12] + swcolsq[2][p2-12] + swcolsq[3][p2-12];
            wj2 = 0.00057339936f * pd * sqrtf(cs) + 1e-6f;
        }
        float m = fmaxf(wj1, wj2);
#pragma unroll
        for (int o = 16; o; o >>= 1) m = fmaxf(m, __shfl_xor_sync(0xffffffffu, m, o));
        float wpdc = 0.f;
        if (p1 != 11) {
            float d = input[n * 62 + p1] - target[n * 62 + p1];
            wpdc += (wj1 / m) * d * d;
        }
        if (p2 < 62) {
            float d = input[n * 62 + p2] - target[n * 62 + p2];
            wpdc += (wj2 / m) * d * d;
        }
        tot += wpdc * (1.f / (128.f * 62.f));
    } else if (tid >= 64 && tid < 264) {
        int t = tid - 64;
        float b0 = bv [3*t], b1 = bv [3*t+1], b2 = bv [3*t+2];
        float c0 = bvg[3*t], c1 = bvg[3*t+1], c2 = bvg[3*t+2];
        float4 o1, o2;
        o1.x = sp [0]*b0 + sp [1]*b1 + sp [2]*b2 + sp [3];
        o1.y = sp [4]*b0 + sp [5]*b1 + sp [6]*b2 + sp [7];
        o1.z = sp [8]*b0 + sp [9]*b1 + sp[10]*b2 + sp[11];
        o1.w = 0.f;
        o2.x = spg[0]*c0 + spg[1]*c1 + spg[2]*c2 + spg[3];
        o2.y = spg[4]*c0 + spg[5]*c1 + spg[6]*c2 + spg[7];
        o2.z = spg[8]*c0 + spg[9]*c1 + spg[10]*c2 + spg[11];
        o2.w = 0.f;
        vt4[t] = o1; vtg4[t] = o2;
    }
    __syncthreads();

    // ---- 3. chamfer on 400 threads (tid 64..463); nwl on warp 15 ----
    const float k_vdc = 3.f * 0.001f / (128.f * 200.f);
    if (tid >= 64 && tid < 264) {
        int t = tid - 64;                 // dir-1: gt query vs pred set
        float4 X = vtg4[t];
        float ma = 3.4e38f, mb = 3.4e38f, mc = 3.4e38f, md = 3.4e38f;
#pragma unroll 2
        for (int k = 0; k < 200; k += 4) {
            float4 a = vt4[k], b = vt4[k+1], c = vt4[k+2], d = vt4[k+3];
            float a0 = X.x-a.x, a1 = X.y-a.y, a2 = X.z-a.z;
            ma = fminf(ma, a0*a0 + a1*a1 + a2*a2);
            float b0 = X.x-b.x, b1 = X.y-b.y, b2 = X.z-b.z;
            mb = fminf(mb, b0*b0 + b1*b1 + b2*b2);
            float c0 = X.x-c.x, c1 = X.y-c.y, c2 = X.z-c.z;
            mc = fminf(mc, c0*c0 + c1*c1 + c2*c2);
            float d0 = X.x-d.x, d1 = X.y-d.y, d2 = X.z-d.z;
            md = fminf(md, d0*d0 + d1*d1 + d2*d2);
        }
        tot += fminf(fminf(ma, mb), fminf(mc, md)) * k_vdc;
    } else if (tid >= 264 && tid < 464) {
        int t = tid - 264;                // dir-2: pred query vs gt set
        float4 Y = vt4[t];
        float ma = 3.4e38f, mb = 3.4e38f, mc = 3.4e38f, md = 3.4e38f;
#pragma unroll 2
        for (int k = 0; k < 200; k += 4) {
            float4 a = vtg4[k], b = vtg4[k+1], c = vtg4[k+2], d = vtg4[k+3];
            float a0 = a.x-Y.x, a1 = a.y-Y.y, a2 = a.z-Y.z;
            ma = fminf(ma, a0*a0 + a1*a1 + a2*a2);
            float b0 = b.x-Y.x, b1 = b.y-Y.y, b2 = b.z-Y.z;
            mb = fminf(mb, b0*b0 + b1*b1 + b2*b2);
            float c0 = c.x-Y.x, c1 = c.y-Y.y, c2 = c.z-Y.z;
            mc = fminf(mc, c0*c0 + c1*c1 + c2*c2);
            float d0 = d.x-Y.x, d1 = d.y-Y.y, d2 = d.z-Y.z;
            md = fminf(md, d0*d0 + d1*d1 + d2*d2);
        }
        tot += fminf(fminf(ma, mb), fminf(mc, md)) * k_vdc;
    } else if (wid == 15) {
        const float k_nwl = 3.f * 0.001f / (128.f * 68.f * 3.f);
        {
            int t = lane;
            float d0 = vtg4[t].x - vt4[t].x;
            float d1 = vtg4[t].y - vt4[t].y;
            float d2 = vtg4[t].z - vt4[t].z;
            tot += ns0 * (d0*d0 + d1*d1 + d2*d2) * k_nwl;
        }
        {
            int t = lane + 32;
            float d0 = vtg4[t].x - vt4[t].x;
            float d1 = vtg4[t].y - vt4[t].y;
            float d2 = vtg4[t].z - vt4[t].z;
            tot += ns1 * (d0*d0 + d1*d1 + d2*d2) * k_nwl;
        }
        if (lane < 4) {
            int t = lane + 64;
            float d0 = vtg4[t].x - vt4[t].x;
            float d1 = vtg4[t].y - vt4[t].y;
            float d2 = vtg4[t].z - vt4[t].z;
            tot += ns2 * (d0*d0 + d1*d1 + d2*d2) * k_nwl;
        }
    }

    // ---- 4. block reduce + finalize (fixed order -> deterministic) ----
    tot = warp_sum(tot);
    if (lane == 0) wsum[wid] = tot;
    __syncthreads();
    if (tid == 0) {
        float b = 0.f;
#pragma unroll
        for (int w = 0; w < 16; w++) b += wsum[w];
        g_partials[n] = b;
        __threadfence();
        unsigned int old = atomicAdd(&g_count, 1u);
        s_last = (old == BATCH - 1);
    }
    __syncthreads();
    if (s_last) {
        __threadfence();
        if (wid == 0) {
            float v = g_partials[lane] + g_partials[lane + 32]
                    + g_partials[lane + 64] + g_partials[lane + 96];
#pragma unroll
            for (int o = 16; o; o >>= 1) v += __shfl_down_sync(0xffffffffu, v, o);
            if (lane == 0) { out[0] = v; g_count = 0; g_pack = 0; }
        }
    }
}

extern "C" void kernel_launch(void* const* d_in, const int* in_sizes, int n_in,
                              void* d_out, int out_size)
{
    (void)in_sizes; (void)n_in; (void)out_size;
    loss_main<<<BATCH + NPACK, NT>>>(
        (const float*)d_in[0],   // input
        (const float*)d_in[1],   // target
        (const float*)d_in[2],   // normals
        (const float*)d_in[3],   // param_mean
        (const float*)d_in[4],   // param_std
        (const float*)d_in[5],   // u
        (const float*)d_in[6],   // w_shp
        (const float*)d_in[7],   // w_exp
        (const int*)d_in[8],     // keyindex
        (const int*)d_in[9],     // resample_idx_w
        (const int*)d_in[10],    // resample_idx_v
        (float*)d_out);
}

// round 9
// speedup vs baseline: 1.2165x; 1.2165x over previous
#include <cuda_runtime.h>

#define BATCH 128
#define NT 512

// ---- dynamic SMEM layout (bytes) ----
#define OFF_S     0                         // float S[996*51]
#define OFF_VT4   203184                    // float4 vt4[200]
#define OFF_VTG4  (OFF_VT4 + 3200)          // float4 vtg4[200]
#define OFF_BV    (OFF_VTG4 + 3200)         // float bv[600]
#define OFF_BVG   (OFF_BV + 2400)           // float bvg[600]
#define OFF_SP    (OFF_BVG + 2400)          // float sp[62]
#define OFF_SPG   (OFF_SP + 248)            // float spg[62]
#define OFF_TNW   (OFF_SPG + 248)           // float tn_w[16][3]
#define OFF_WCS   (OFF_TNW + 192)           // float swcolsq[4][50]
#define OFF_WSUM  (OFF_WCS + 800)           // float wsum[16]
#define OFF_SIDX  (OFF_WSUM + 64)           // int sidx[332]
#define OFF_LAST  (OFF_SIDX + 1328)         // int s_last
#define SMEM_BYTES (OFF_LAST + 16)

__device__ float g_partials[BATCH];
__device__ unsigned int g_count = 0;

__device__ __forceinline__ float warp_sum(float v) {
#pragma unroll
    for (int o = 16; o; o >>= 1) v += __shfl_down_sync(0xffffffffu, v, o);
    return v;
}

// grid = 128 blocks, one per batch element. Large dynamic SMEM stages the basis.
__global__ __launch_bounds__(NT, 1)
void loss_main(const float* __restrict__ input,
               const float* __restrict__ target,
               const float* __restrict__ normals,
               const float* __restrict__ param_mean,
               const float* __restrict__ param_std,
               const float* __restrict__ u,
               const float* __restrict__ w_shp,
               const float* __restrict__ w_exp,
               const int*   __restrict__ keyindex,
               const int*   __restrict__ ridx_w,
               const int*   __restrict__ ridx_v,
               float* __restrict__ out)
{
    extern __shared__ char smem[];
    float*  S     = (float*)(smem + OFF_S);      // S[row*51 + c]: c0=u, c1..40=w_shp, c41..50=w_exp
    float4* vt4   = (float4*)(smem + OFF_VT4);
    float4* vtg4  = (float4*)(smem + OFF_VTG4);
    float*  bv    = (float*)(smem + OFF_BV);
    float*  bvg   = (float*)(smem + OFF_BVG);
    float*  sp    = (float*)(smem + OFF_SP);
    float*  spg   = (float*)(smem + OFF_SPG);
    float*  tn_w  = (float*)(smem + OFF_TNW);    // [16][3]
    float*  swcs  = (float*)(smem + OFF_WCS);    // [4][50]
    float*  wsum  = (float*)(smem + OFF_WSUM);
    int*    sidx  = (int*)(smem + OFF_SIDX);     // [0,68) key | [68,200) ridx_w | [200,332) ridx_v
    int*    s_last= (int*)(smem + OFF_LAST);

    const int n    = blockIdx.x;
    const int tid  = threadIdx.x;
    const int lane = tid & 31;
    const int wid  = tid >> 5;

    // ---- 0. params + indices ----
    if (tid < 62) {
        float st = param_std[tid], mn = param_mean[tid];
        sp[tid]  = input [n * 62 + tid] * st + mn;
        spg[tid] = target[n * 62 + tid] * st + mn;
    } else if (tid >= 64 && tid < 396) {
        int j = tid - 64;
        sidx[j] = (j < 68) ? keyindex[j] : (j < 200 ? ridx_w[j - 68] : ridx_v[j - 200]);
    }
    __syncthreads();

    // ---- 1. copy phase (warps 0..14, coalesced/vectorized) ; warp 15: normals colsums ----
    float ns0 = 0.f, ns1 = 0.f, ns2 = 0.f;
    if (wid < 15) {
        const int NTC = 480;
        // u column: 996 scalars
        for (int i = tid; i < 996; i += NTC) {
            int j = i / 3, cc = i - 3 * j;
            S[i * 51] = u[3 * (size_t)sidx[j] + cc];
        }
        // w_shp: 996 rows x 10 float4
        const float4* w4 = (const float4*)w_shp;
#pragma unroll 2
        for (int e = tid; e < 9960; e += NTC) {
            int row = e / 10, f = e - 10 * row;
            int j = row / 3, cc = row - 3 * j;
            size_t r3 = 3 * (size_t)sidx[j] + cc;
            float4 v = w4[r3 * 10 + f];
            float* d = S + row * 51 + 1 + 4 * f;
            d[0] = v.x; d[1] = v.y; d[2] = v.z; d[3] = v.w;
        }
        // w_exp: 996 rows x 5 float2
        const float2* e2 = (const float2*)w_exp;
#pragma unroll 2
        for (int e = tid; e < 4980; e += NTC) {
            int row = e / 5, f = e - 5 * row;
            int j = row / 3, cc = row - 3 * j;
            size_t r3 = 3 * (size_t)sidx[j] + cc;
            float2 v = e2[r3 * 5 + f];
            float* d = S + row * 51 + 41 + 2 * f;
            d[0] = v.x; d[1] = v.y;
        }
    } else {
        // warp 15: normals column sums (coalesced rows), kept in registers
        const float* nb = normals + (size_t)n * (68 * 68);
#pragma unroll 4
        for (int i = 0; i < 68; i++) {
            const float* rowp = nb + i * 68;
            ns0 += rowp[lane];
            ns1 += rowp[lane + 32];
            if (lane < 4) ns2 += rowp[lane + 64];
        }
    }
    __syncthreads();

    // ---- 2. dot phase from SMEM: 996 row jobs + 200 wcol jobs ----
    //   rows [0,204): pred+gt -> bv/bvg[l], + tn        (keypoints, shared w/v)
    //   rows [204,600): pred -> tn                       (ridx_w)
    //   rows [600,996): pred+gt -> bv/bvg[l-396]         (ridx_v)
    float tn0 = 0.f, tn1 = 0.f, tn2 = 0.f;
#pragma unroll 1
    for (int l = tid; l < 1196; l += NT) {
        if (l < 996) {
            const float* Sr = S + l * 51;
            float u0 = Sr[0];
            bool dual = (l < 204) || (l >= 600);
            if (dual) {
                float pa = u0, pb = 0.f, ga = u0, gb = 0.f;
#pragma unroll
                for (int c = 0; c < 50; c += 2) {
                    float va = Sr[1 + c], vb = Sr[2 + c];
                    pa += va * sp [12 + c];  pb += vb * sp [13 + c];
                    ga += va * spg[12 + c];  gb += vb * spg[13 + c];
                }
                float s = pa + pb, g = ga + gb;
                int d = (l < 204) ? l : l - 396;
                bv[d] = s; bvg[d] = g;
                if (l < 204) {
                    float s2 = s * s;
                    int c3 = l % 3;
                    if (c3 == 0) tn0 += s2; else if (c3 == 1) tn1 += s2; else tn2 += s2;
                }
            } else {
                float pa = u0, pb = 0.f;
#pragma unroll
                for (int c = 0; c < 50; c += 2) {
                    pa += Sr[1 + c] * sp[12 + c];
                    pb += Sr[2 + c] * sp[13 + c];
                }
                float s = pa + pb;
                float s2 = s * s;
                int c3 = l % 3;
                if (c3 == 0) tn0 += s2; else if (c3 == 1) tn1 += s2; else tn2 += s2;
            }
        } else {
            // wcol quarter: col c over rows [h*150,(h+1)*150), S col 1+c
            int idx = l - 996;
            int c = idx % 50, h = idx / 50;
            const float* p = S + (size_t)(h * 150) * 51 + 1 + c;
            float a0 = 0.f, a1 = 0.f;
#pragma unroll 6
            for (int i = 0; i < 150; i += 2) {
                float x = p[i * 51];
                float y = p[(i + 1) * 51];
                a0 += x * x; a1 += y * y;
            }
            swcs[h * 50 + c] = a0 + a1;
        }
    }
    tn0 = warp_sum(tn0); tn1 = warp_sum(tn1); tn2 = warp_sum(tn2);
    if (lane == 0) { tn_w[wid * 3 + 0] = tn0; tn_w[wid * 3 + 1] = tn1; tn_w[wid * 3 + 2] = tn2; }
    __syncthreads();

    // ---- 3. warp 0: weights + wpdc; tid 64..263: rotate verts ----
    float tot = 0.f;
    if (wid == 0) {
        int p1 = lane, p2 = lane + 32;
        float wj1, wj2 = 0.f;
        {
            float pd = fabsf(sp[p1] - spg[p1]);
            if (p1 < 11) {
                int cc = p1 & 3;
                float sc;
                if (cc < 3) {
                    float t = 0.f;
#pragma unroll
                    for (int w = 0; w < 16; w++) t += tn_w[w * 3 + cc];
                    sc = sqrtf(t);
                } else sc = 14.142135623730951f;   // sqrt(200)
                wj1 = pd * sc + 1e-6f;
            } else if (p1 == 11) wj1 = 1e-6f;
            else {
                float cs = swcs[p1-12] + swcs[50+p1-12] + swcs[100+p1-12] + swcs[150+p1-12];
                wj1 = 0.00057339936f * pd * sqrtf(cs) + 1e-6f;
            }
        }
        if (p2 < 62) {
            float pd = fabsf(sp[p2] - spg[p2]);
            float cs = swcs[p2-12] + swcs[50+p2-12] + swcs[100+p2-12] + swcs[150+p2-12];
            wj2 = 0.00057339936f * pd * sqrtf(cs) + 1e-6f;
        }
        float m = fmaxf(wj1, wj2);
#pragma unroll
        for (int o = 16; o; o >>= 1) m = fmaxf(m, __shfl_xor_sync(0xffffffffu, m, o));
        float wpdc = 0.f;
        if (p1 != 11) {
            float d = input[n * 62 + p1] - target[n * 62 + p1];
            wpdc += (wj1 / m) * d * d;
        }
        if (p2 < 62) {
            float d = input[n * 62 + p2] - target[n * 62 + p2];
            wpdc += (wj2 / m) * d * d;
        }
        tot += wpdc * (1.f / (128.f * 62.f));
    } else if (tid >= 64 && tid < 264) {
        int t = tid - 64;
        float b0 = bv [3*t], b1 = bv [3*t+1], b2 = bv [3*t+2];
        float c0 = bvg[3*t], c1 = bvg[3*t+1], c2 = bvg[3*t+2];
        float4 o1, o2;
        o1.x = sp [0]*b0 + sp [1]*b1 + sp [2]*b2 + sp [3];
        o1.y = sp [4]*b0 + sp [5]*b1 + sp [6]*b2 + sp [7];
        o1.z = sp [8]*b0 + sp [9]*b1 + sp[10]*b2 + sp[11];
        o1.w = 0.f;
        o2.x = spg[0]*c0 + spg[1]*c1 + spg[2]*c2 + spg[3];
        o2.y = spg[4]*c0 + spg[5]*c1 + spg[6]*c2 + spg[7];
        o2.z = spg[8]*c0 + spg[9]*c1 + spg[10]*c2 + spg[11];
        o2.w = 0.f;
        vt4[t] = o1; vtg4[t] = o2;
    }
    __syncthreads();

    // ---- 4. chamfer on 400 threads (tid 64..463); nwl on warp 15 ----
    const float k_vdc = 3.f * 0.001f / (128.f * 200.f);
    if (tid >= 64 && tid < 264) {
        int t = tid - 64;                 // dir-1: gt query vs pred set
        float4 X = vtg4[t];
        float ma = 3.4e38f, mb = 3.4e38f, mc = 3.4e38f, md = 3.4e38f;
#pragma unroll 2
        for (int k = 0; k < 200; k += 4) {
            float4 a = vt4[k], b = vt4[k+1], c = vt4[k+2], d = vt4[k+3];
            float a0 = X.x-a.x, a1 = X.y-a.y, a2 = X.z-a.z;
            ma = fminf(ma, a0*a0 + a1*a1 + a2*a2);
            float b0 = X.x-b.x, b1 = X.y-b.y, b2 = X.z-b.z;
            mb = fminf(mb, b0*b0 + b1*b1 + b2*b2);
            float c0 = X.x-c.x, c1 = X.y-c.y, c2 = X.z-c.z;
            mc = fminf(mc, c0*c0 + c1*c1 + c2*c2);
            float d0 = X.x-d.x, d1 = X.y-d.y, d2 = X.z-d.z;
            md = fminf(md, d0*d0 + d1*d1 + d2*d2);
        }
        tot += fminf(fminf(ma, mb), fminf(mc, md)) * k_vdc;
    } else if (tid >= 264 && tid < 464) {
        int t = tid - 264;                // dir-2: pred query vs gt set
        float4 Y = vt4[t];
        float ma = 3.4e38f, mb = 3.4e38f, mc = 3.4e38f, md = 3.4e38f;
#pragma unroll 2
        for (int k = 0; k < 200; k += 4) {
            float4 a = vtg4[k], b = vtg4[k+1], c = vtg4[k+2], d = vtg4[k+3];
            float a0 = a.x-Y.x, a1 = a.y-Y.y, a2 = a.z-Y.z;
            ma = fminf(ma, a0*a0 + a1*a1 + a2*a2);
            float b0 = b.x-Y.x, b1 = b.y-Y.y, b2 = b.z-Y.z;
            mb = fminf(mb, b0*b0 + b1*b1 + b2*b2);
            float c0 = c.x-Y.x, c1 = c.y-Y.y, c2 = c.z-Y.z;
            mc = fminf(mc, c0*c0 + c1*c1 + c2*c2);
            float d0 = d.x-Y.x, d1 = d.y-Y.y, d2 = d.z-Y.z;
            md = fminf(md, d0*d0 + d1*d1 + d2*d2);
        }
        tot += fminf(fminf(ma, mb), fminf(mc, md)) * k_vdc;
    } else if (wid == 15) {
        const float k_nwl = 3.f * 0.001f / (128.f * 68.f * 3.f);
        {
            int t = lane;
            float d0 = vtg4[t].x - vt4[t].x;
            float d1 = vtg4[t].y - vt4[t].y;
            float d2 = vtg4[t].z - vt4[t].z;
            tot += ns0 * (d0*d0 + d1*d1 + d2*d2) * k_nwl;
        }
        {
            int t = lane + 32;
            float d0 = vtg4[t].x - vt4[t].x;
            float d1 = vtg4[t].y - vt4[t].y;
            float d2 = vtg4[t].z - vt4[t].z;
            tot += ns1 * (d0*d0 + d1*d1 + d2*d2) * k_nwl;
        }
        if (lane < 4) {
            int t = lane + 64;
            float d0 = vtg4[t].x - vt4[t].x;
            float d1 = vtg4[t].y - vt4[t].y;
            float d2 = vtg4[t].z - vt4[t].z;
            tot += ns2 * (d0*d0 + d1*d1 + d2*d2) * k_nwl;
        }
    }

    // ---- 5. block reduce + finalize (fixed order -> deterministic) ----
    tot = warp_sum(tot);
    if (lane == 0) wsum[wid] = tot;
    __syncthreads();
    if (tid == 0) {
        float b = 0.f;
#pragma unroll
        for (int w = 0; w < 16; w++) b += wsum[w];
        g_partials[n] = b;
        __threadfence();
        unsigned int old = atomicAdd(&g_count, 1u);
        *s_last = (old == BATCH - 1);
    }
    __syncthreads();
    if (*s_last) {
        __threadfence();
        if (wid == 0) {
            float v = g_partials[lane] + g_partials[lane + 32]
                    + g_partials[lane + 64] + g_partials[lane + 96];
#pragma unroll
            for (int o = 16; o; o >>= 1) v += __shfl_down_sync(0xffffffffu, v, o);
            if (lane == 0) { out[0] = v; g_count = 0; }
        }
    }
}

extern "C" void kernel_launch(void* const* d_in, const int* in_sizes, int n_in,
                              void* d_out, int out_size)
{
    (void)in_sizes; (void)n_in; (void)out_size;
    cudaFuncSetAttribute(loss_main, cudaFuncAttributeMaxDynamicSharedMemorySize, SMEM_BYTES);
    loss_main<<<BATCH, NT, SMEM_BYTES>>>(
        (const float*)d_in[0],   // input
        (const float*)d_in[1],   // target
        (const float*)d_in[2],   // normals
        (const float*)d_in[3],   // param_mean
        (const float*)d_in[4],   // param_std
        (const float*)d_in[5],   // u
        (const float*)d_in[6],   // w_shp
        (const float*)d_in[7],   // w_exp
        (const int*)d_in[8],     // keyindex
        (const int*)d_in[9],     // resample_idx_w
        (const int*)d_in[10],    // resample_idx_v
        (float*)d_out);
}

// round 10
// speedup vs baseline: 1.3631x; 1.1206x over previous
#include <cuda_runtime.h>

#define BATCH 128
#define NT 512

__device__ float g_partials[BATCH];
__device__ float g_wcol[50];
__device__ unsigned int g_count = 0;
__device__ int g_wflag = 0;

__device__ __forceinline__ float warp_sum(float v) {
#pragma unroll
    for (int o = 16; o; o >>= 1) v += __shfl_down_sync(0xffffffffu, v, o);
    return v;
}

// grid = BATCH+1. Blocks 0..127: one batch element. Block 128: w_cat column norms.
__global__ __launch_bounds__(NT, 1)
void loss_main(const float* __restrict__ input,
               const float* __restrict__ target,
               const float* __restrict__ normals,
               const float* __restrict__ param_mean,
               const float* __restrict__ param_std,
               const float* __restrict__ u,
               const float* __restrict__ w_shp,
               const float* __restrict__ w_exp,
               const int*   __restrict__ keyindex,
               const int*   __restrict__ ridx_w,
               const int*   __restrict__ ridx_v,
               float* __restrict__ out)
{
    const int tid  = threadIdx.x;
    const int lane = tid & 31;
    const int wid  = tid >> 5;

    // ============ dedicated block: batch-independent w_cat column norms ============
    if (blockIdx.x == BATCH) {
        __shared__ int srow[600];
        __shared__ float cpart[16][50];
        for (int l = tid; l < 600; l += NT) {
            int j = l / 3, c = l - 3 * j;
            int vid = (j < 68) ? keyindex[j] : ridx_w[j - 68];
            srow[l] = 3 * vid + c;
        }
        __syncthreads();
        float a1 = 0.f, a2 = 0.f;
        const int c1 = lane;
        const int c2 = lane + 32;
#pragma unroll 2
        for (int rr = wid; rr < 600; rr += 16) {
            size_t r = (size_t)srow[rr];
            float v1 = w_shp[r * 40 + c1];
            a1 += v1 * v1;
            if (c2 < 50) {
                float v2 = (c2 < 40) ? w_shp[r * 40 + c2] : w_exp[r * 10 + (c2 - 40)];
                a2 += v2 * v2;
            }
        }
        cpart[wid][c1] = a1;
        if (c2 < 50) cpart[wid][c2] = a2;
        __syncthreads();
        if (tid < 50) {
            float s = 0.f;
#pragma unroll
            for (int w = 0; w < 16; w++) s += cpart[w][tid];
            g_wcol[tid] = sqrtf(s);
        }
        __threadfence();
        __syncthreads();
        if (tid == 0) atomicExch(&g_wflag, 1);
        return;
    }

    // ============ per-batch block ============
    const int n = blockIdx.x;

    __shared__ float sp[62], spg[62];
    __shared__ float bv[600], bvg[600];
    __shared__ float tn_w[16][3];
    __shared__ float tnsq[3];
    __shared__ float4 vt4[200], vtg4[200];   // .w = |xyz|^2
    __shared__ float wsum[16];
    __shared__ int   s_last;

    // ---- 0. denormalize params ----
    if (tid < 62) {
        float st = param_std[tid], mn = param_mean[tid];
        sp[tid]  = input [n * 62 + tid] * st + mn;
        spg[tid] = target[n * 62 + tid] * st + mn;
    }
    __syncthreads();

    // ---- 1. merged gather region: 1200 items, one barrier. ----
    float tn0 = 0.f, tn1 = 0.f, tn2 = 0.f;
#pragma unroll 1
    for (int l = tid; l < 1200; l += NT) {
        if (l < 396) {
            int row = 204 + l;
            int j = row / 3, c = row - 3 * j;
            size_t r = 3 * (size_t)ridx_v[j - 68] + c;
            const float4* w4 = (const float4*)(w_shp + r * 40);
            const float2* e2 = (const float2*)(w_exp + r * 10);
            float uu = u[r];
            float sa = uu, sb = 0.f, ga = uu, gb = 0.f;
#pragma unroll
            for (int q = 0; q < 10; q += 2) {
                float4 v0 = w4[q], v1 = w4[q + 1];
                sa += v0.x*sp [12+4*q] + v0.y*sp [13+4*q] + v0.z*sp [14+4*q] + v0.w*sp [15+4*q];
                sb += v1.x*sp [16+4*q] + v1.y*sp [17+4*q] + v1.z*sp [18+4*q] + v1.w*sp [19+4*q];
                ga += v0.x*spg[12+4*q] + v0.y*spg[13+4*q] + v0.z*spg[14+4*q] + v0.w*spg[15+4*q];
                gb += v1.x*spg[16+4*q] + v1.y*spg[17+4*q] + v1.z*spg[18+4*q] + v1.w*spg[19+4*q];
            }
#pragma unroll
            for (int q = 0; q < 5; q++) {
                float2 v = e2[q];
                sa += v.x*sp [52+2*q] + v.y*sp [53+2*q];
                ga += v.x*spg[52+2*q] + v.y*spg[53+2*q];
            }
            bv[row] = sa + sb; bvg[row] = ga + gb;
        } else if (l < 996) {
            int m = l - 396;
            int j = m / 3, c = m - 3 * j;
            int vid = (j < 68) ? keyindex[j] : ridx_w[j - 68];
            size_t r = 3 * (size_t)vid + c;
            const float4* w4 = (const float4*)(w_shp + r * 40);
            const float2* e2 = (const float2*)(w_exp + r * 10);
            float sa = u[r], sb = 0.f;
#pragma unroll
            for (int q = 0; q < 10; q += 2) {
                float4 v0 = w4[q], v1 = w4[q + 1];
                sa += v0.x*sp[12+4*q] + v0.y*sp[13+4*q] + v0.z*sp[14+4*q] + v0.w*sp[15+4*q];
                sb += v1.x*sp[16+4*q] + v1.y*sp[17+4*q] + v1.z*sp[18+4*q] + v1.w*sp[19+4*q];
            }
#pragma unroll
            for (int q = 0; q < 5; q++) {
                float2 v = e2[q];
                sa += v.x*sp[52+2*q] + v.y*sp[53+2*q];
            }
            float s = sa + sb;
            if (m < 204) bv[m] = s;
            float s2 = s * s;
            if (c == 0) tn0 += s2; else if (c == 1) tn1 += s2; else tn2 += s2;
        } else {
            int m = l - 996;
            int j = m / 3, c = m - 3 * j;
            size_t r = 3 * (size_t)keyindex[j] + c;
            const float4* w4 = (const float4*)(w_shp + r * 40);
            const float2* e2 = (const float2*)(w_exp + r * 10);
            float ga = u[r], gb = 0.f;
#pragma unroll
            for (int q = 0; q < 10; q += 2) {
                float4 v0 = w4[q], v1 = w4[q + 1];
                ga += v0.x*spg[12+4*q] + v0.y*spg[13+4*q] + v0.z*spg[14+4*q] + v0.w*spg[15+4*q];
                gb += v1.x*spg[16+4*q] + v1.y*spg[17+4*q] + v1.z*spg[18+4*q] + v1.w*spg[19+4*q];
            }
#pragma unroll
            for (int q = 0; q < 5; q++) {
                float2 v = e2[q];
                ga += v.x*spg[52+2*q] + v.y*spg[53+2*q];
            }
            bvg[m] = ga + gb;
        }
    }
    tn0 = warp_sum(tn0); tn1 = warp_sum(tn1); tn2 = warp_sum(tn2);
    if (lane == 0) { tn_w[wid][0] = tn0; tn_w[wid][1] = tn1; tn_w[wid][2] = tn2; }
    __syncthreads();

    // ---- 2. fold tn, rotate verts (+squared norms in .w), wait for wcol flag ----
    if (tid < 3) {
        float s = 0.f;
#pragma unroll
        for (int w = 0; w < 16; w++) s += tn_w[w][tid];
        tnsq[tid] = s;
    }
    if (tid >= 256 && tid < 456) {
        int t = tid - 256;
        float b0 = bv [3*t], b1 = bv [3*t+1], b2 = bv [3*t+2];
        float c0 = bvg[3*t], c1 = bvg[3*t+1], c2 = bvg[3*t+2];
        float4 o1, o2;
        o1.x = sp [0]*b0 + sp [1]*b1 + sp [2]*b2 + sp [3];
        o1.y = sp [4]*b0 + sp [5]*b1 + sp [6]*b2 + sp [7];
        o1.z = sp [8]*b0 + sp [9]*b1 + sp[10]*b2 + sp[11];
        o1.w = o1.x*o1.x + o1.y*o1.y + o1.z*o1.z;
        o2.x = spg[0]*c0 + spg[1]*c1 + spg[2]*c2 + spg[3];
        o2.y = spg[4]*c0 + spg[5]*c1 + spg[6]*c2 + spg[7];
        o2.z = spg[8]*c0 + spg[9]*c1 + spg[10]*c2 + spg[11];
        o2.w = o2.x*o2.x + o2.y*o2.y + o2.z*o2.z;
        vt4[t] = o1; vtg4[t] = o2;
    }
    if (tid == 32) {
        while (atomicAdd(&g_wflag, 0) == 0) __nanosleep(64);
    }
    __syncthreads();
    __threadfence();  // acquire for g_wcol

    // ---- 3. one region: warp0 weights+wpdc; chamfer tid 96..195 & 256..355; nwl 416..483 ----
    float tot = 0.f;
    if (wid == 0) {
        int p1 = lane, p2 = lane + 32;
        float wj1, wj2 = 0.f;
        {
            float pd = fabsf(sp[p1] - spg[p1]);
            if (p1 < 11) {
                int cc = p1 & 3;
                float sc = (cc < 3) ? sqrtf(tnsq[cc]) : 14.142135623730951f;
                wj1 = pd * sc + 1e-6f;
            } else if (p1 == 11) wj1 = 1e-6f;
            else wj1 = 0.00057339936f * pd * g_wcol[p1 - 12] + 1e-6f;
        }
        if (p2 < 62) {
            float pd = fabsf(sp[p2] - spg[p2]);
            wj2 = 0.00057339936f * pd * g_wcol[p2 - 12] + 1e-6f;
        }
        float m = fmaxf(wj1, wj2);
#pragma unroll
        for (int o = 16; o; o >>= 1) m = fmaxf(m, __shfl_xor_sync(0xffffffffu, m, o));
        float wpdc = 0.f;
        if (p1 != 11) {
            float d = input[n * 62 + p1] - target[n * 62 + p1];
            wpdc += (wj1 / m) * d * d;
        }
        if (p2 < 62) {
            float d = input[n * 62 + p2] - target[n * 62 + p2];
            wpdc += (wj2 / m) * d * d;
        }
        tot += wpdc * (1.f / (128.f * 62.f));
    } else if (tid >= 96 && tid < 196) {
        // chamfer dir-1: gt queries t, t+100 vs pred set. d2 = X.w + min_k(a.w - 2 X.a)
        int t = tid - 96;
        float4 X1 = vtg4[t], X2 = vtg4[t + 100];
        float x1x = -2.f*X1.x, x1y = -2.f*X1.y, x1z = -2.f*X1.z;
        float x2x = -2.f*X2.x, x2y = -2.f*X2.y, x2z = -2.f*X2.z;
        float m1a = 3.4e38f, m1b = 3.4e38f, m2a = 3.4e38f, m2b = 3.4e38f;
#pragma unroll 4
        for (int k = 0; k < 200; k += 2) {
            float4 a = vt4[k], b = vt4[k + 1];
            m1a = fminf(m1a, fmaf(x1x, a.x, fmaf(x1y, a.y, fmaf(x1z, a.z, a.w))));
            m1b = fminf(m1b, fmaf(x1x, b.x, fmaf(x1y, b.y, fmaf(x1z, b.z, b.w))));
            m2a = fminf(m2a, fmaf(x2x, a.x, fmaf(x2y, a.y, fmaf(x2z, a.z, a.w))));
            m2b = fminf(m2b, fmaf(x2x, b.x, fmaf(x2y, b.y, fmaf(x2z, b.z, b.w))));
        }
        float d1 = X1.w + fminf(m1a, m1b);
        float d2 = X2.w + fminf(m2a, m2b);
        tot += (d1 + d2) * (3.f * 0.001f / (128.f * 200.f));
    } else if (tid >= 256 && tid < 356) {
        // chamfer dir-2: pred queries t, t+100 vs gt set
        int t = tid - 256;
        float4 Y1 = vt4[t], Y2 = vt4[t + 100];
        float y1x = -2.f*Y1.x, y1y = -2.f*Y1.y, y1z = -2.f*Y1.z;
        float y2x = -2.f*Y2.x, y2y = -2.f*Y2.y, y2z = -2.f*Y2.z;
        float m1a = 3.4e38f, m1b = 3.4e38f, m2a = 3.4e38f, m2b = 3.4e38f;
#pragma unroll 4
        for (int k = 0; k < 200; k += 2) {
            float4 a = vtg4[k], b = vtg4[k + 1];
            m1a = fminf(m1a, fmaf(y1x, a.x, fmaf(y1y, a.y, fmaf(y1z, a.z, a.w))));
            m1b = fminf(m1b, fmaf(y1x, b.x, fmaf(y1y, b.y, fmaf(y1z, b.z, b.w))));
            m2a = fminf(m2a, fmaf(y2x, a.x, fmaf(y2y, a.y, fmaf(y2z, a.z, a.w))));
            m2b = fminf(m2b, fmaf(y2x, b.x, fmaf(y2y, b.y, fmaf(y2z, b.z, b.w))));
        }
        float d1 = Y1.w + fminf(m1a, m1b);
        float d2 = Y2.w + fminf(m2a, m2b);
        tot += (d1 + d2) * (3.f * 0.001f / (128.f * 200.f));
    } else if (tid >= 416 && tid < 484) {
        // nwl: thread t owns landmark/column t
        int t = tid - 416;
        const float* nb = normals + (size_t)n * (68 * 68) + t;
        float a0 = 0.f, a1 = 0.f, a2 = 0.f, a3 = 0.f;
#pragma unroll
        for (int i = 0; i < 68; i += 4) {
            a0 += nb[(i + 0) * 68];
            a1 += nb[(i + 1) * 68];
            a2 += nb[(i + 2) * 68];
            a3 += nb[(i + 3) * 68];
        }
        float s = (a0 + a1) + (a2 + a3);
        float d0 = vtg4[t].x - vt4[t].x;
        float d1 = vtg4[t].y - vt4[t].y;
        float d2 = vtg4[t].z - vt4[t].z;
        tot += s * (d0*d0 + d1*d1 + d2*d2) * (3.f * 0.001f / (128.f * 68.f * 3.f));
    }

    // ---- 4. block reduce + finalize ----
    tot = warp_sum(tot);
    if (lane == 0) wsum[wid] = tot;
    __syncthreads();
    if (tid == 0) {
        float b = 0.f;
#pragma unroll
        for (int w = 0; w < 16; w++) b += wsum[w];
        g_partials[n] = b;
        __threadfence();
        unsigned int old = atomicAdd(&g_count, 1u);
        s_last = (old == BATCH - 1);
    }
    __syncthreads();
    if (s_last) {
        __threadfence();
        if (wid == 0) {
            float v = g_partials[lane] + g_partials[lane + 32]
                    + g_partials[lane + 64] + g_partials[lane + 96];
#pragma unroll
            for (int o = 16; o; o >>= 1) v += __shfl_down_sync(0xffffffffu, v, o);
            if (lane == 0) { out[0] = v; g_count = 0; g_wflag = 0; }
        }
    }
}

extern "C" void kernel_launch(void* const* d_in, const int* in_sizes, int n_in,
                              void* d_out, int out_size)
{
    (void)in_sizes; (void)n_in; (void)out_size;
    loss_main<<<BATCH + 1, NT>>>(
        (const float*)d_in[0],   // input
        (const float*)d_in[1],   // target
        (const float*)d_in[2],   // normals
        (const float*)d_in[3],   // param_mean
        (const float*)d_in[4],   // param_std
        (const float*)d_in[5],   // u
        (const float*)d_in[6],   // w_shp
        (const float*)d_in[7],   // w_exp
        (const int*)d_in[8],     // keyindex
        (const int*)d_in[9],     // resample_idx_w
        (const int*)d_in[10],    // resample_idx_v
        (float*)d_out);
}

// round 11
// speedup vs baseline: 1.4694x; 1.0780x over previous
#include <cuda_runtime.h>

#define BATCH 128
#define NT 512
#define S_BYTES (996 * 52 * 4)

__device__ float g_partials[BATCH];
__device__ float g_wcol[50];
__device__ unsigned int g_count = 0;
__device__ int g_wflag = 0;

__device__ __forceinline__ float warp_sum(float v) {
#pragma unroll
    for (int o = 16; o; o >>= 1) v += __shfl_down_sync(0xffffffffu, v, o);
    return v;
}

// grid = BATCH+1. Blocks 0..127: one batch element. Block 128: w_cat column norms.
__global__ __launch_bounds__(NT, 1)
void loss_main(const float* __restrict__ input,
               const float* __restrict__ target,
               const float* __restrict__ normals,
               const float* __restrict__ param_mean,
               const float* __restrict__ param_std,
               const float* __restrict__ u,
               const float* __restrict__ w_shp,
               const float* __restrict__ w_exp,
               const int*   __restrict__ keyindex,
               const int*   __restrict__ ridx_w,
               const int*   __restrict__ ridx_v,
               float* __restrict__ out)
{
    const int tid  = threadIdx.x;
    const int lane = tid & 31;
    const int wid  = tid >> 5;

    // ============ dedicated block: batch-independent w_cat column norms ============
    if (blockIdx.x == BATCH) {
        __shared__ int srw[600];
        __shared__ float cpart[16][50];
        for (int l = tid; l < 600; l += NT) {
            int j = l / 3, c = l - 3 * j;
            int vid = (j < 68) ? keyindex[j] : ridx_w[j - 68];
            srw[l] = 3 * vid + c;
        }
        __syncthreads();
        float a1 = 0.f, a2 = 0.f;
        const int c1 = lane;
        const int c2 = lane + 32;
#pragma unroll 2
        for (int rr = wid; rr < 600; rr += 16) {
            size_t r = (size_t)srw[rr];
            float v1 = w_shp[r * 40 + c1];
            a1 += v1 * v1;
            if (c2 < 50) {
                float v2 = (c2 < 40) ? w_shp[r * 40 + c2] : w_exp[r * 10 + (c2 - 40)];
                a2 += v2 * v2;
            }
        }
        cpart[wid][c1] = a1;
        if (c2 < 50) cpart[wid][c2] = a2;
        __syncthreads();
        if (tid < 50) {
            float s = 0.f;
#pragma unroll
            for (int w = 0; w < 16; w++) s += cpart[w][tid];
            g_wcol[tid] = sqrtf(s);
        }
        __threadfence();
        __syncthreads();
        if (tid == 0) atomicExch(&g_wflag, 1);
        return;
    }

    // ============ per-batch block ============
    const int n = blockIdx.x;

    extern __shared__ float S[];       // S[row*52 + c]: c0..49 = wshp|wexp, c50 = u, c51 pad
    __shared__ float sp[62], spg[62];
    __shared__ int   sidx[332];        // [0,68) key | [68,200) ridx_w | [200,332) ridx_v
    __shared__ int   srow[996];        // global row index (3*vid+cc) per S row
    __shared__ float bv[600], bvg[600];
    __shared__ float tn_w[16][3];
    __shared__ float tnsq[3];
    __shared__ float4 vt4[200], vtg4[200];   // .w = |xyz|^2
    __shared__ float wsum[16];
    __shared__ int   s_last;

    // ---- 0a. params + indices ----
    if (tid < 62) {
        float st = param_std[tid], mn = param_mean[tid];
        sp[tid]  = input [n * 62 + tid] * st + mn;
        spg[tid] = target[n * 62 + tid] * st + mn;
    } else if (tid >= 64 && tid < 396) {
        int j = tid - 64;
        sidx[j] = (j < 68) ? keyindex[j] : (j < 200 ? ridx_w[j - 68] : ridx_v[j - 200]);
    }
    __syncthreads();

    // ---- 0b. per-row global addresses ----
    // S rows: [0,204) keypoints | [204,600) ridx_v | [600,996) ridx_w
    for (int i = tid; i < 996; i += NT) {
        int vid, cc;
        if (i < 204)      { vid = sidx[i / 3];             cc = i % 3; }
        else if (i < 600) { int m = i - 204; vid = sidx[200 + m / 3]; cc = m % 3; }
        else              { int m = i - 600; vid = sidx[68 + m / 3];  cc = m % 3; }
        srow[i] = 3 * vid + cc;
    }
    __syncthreads();

    // ---- 1. coalesced copy (warps 0..14) ; warp 15: normals column sums ----
    float ns0 = 0.f, ns1 = 0.f, ns2 = 0.f;
    if (wid < 15) {
        const int NTC = 480;
        const float4* w4 = (const float4*)w_shp;
#pragma unroll 2
        for (int e = tid; e < 9960; e += NTC) {
            int row = e / 10, f = e - 10 * row;
            float4 v = w4[(size_t)srow[row] * 10 + f];
            *(float4*)(S + row * 52 + 4 * f) = v;
        }
        const float2* e2 = (const float2*)w_exp;
#pragma unroll 2
        for (int e = tid; e < 4980; e += NTC) {
            int row = e / 5, f = e - 5 * row;
            float2 v = e2[(size_t)srow[row] * 5 + f];
            *(float2*)(S + row * 52 + 40 + 2 * f) = v;
        }
        for (int i = tid; i < 996; i += NTC) {
            S[i * 52 + 50] = u[srow[i]];
        }
    } else {
        const float* nb = normals + (size_t)n * (68 * 68);
#pragma unroll 4
        for (int i = 0; i < 68; i++) {
            const float* rowp = nb + i * 68;
            ns0 += rowp[lane];
            ns1 += rowp[lane + 32];
            if (lane < 4) ns2 += rowp[lane + 64];
        }
    }
    __syncthreads();

    // ---- 2. dot phase from SMEM: 996 row jobs (conflict-free LDS.128) ----
    float tn0 = 0.f, tn1 = 0.f, tn2 = 0.f;
#pragma unroll 1
    for (int l = tid; l < 996; l += NT) {
        const float4* Sr = (const float4*)(S + l * 52);
        if (l < 600) {
            // dual pred+gt
            float pa = 0.f, pb = 0.f, ga = 0.f, gb = 0.f;
#pragma unroll
            for (int f = 0; f < 12; f++) {
                float4 x = Sr[f];
                pa += x.x * sp [12 + 4*f] + x.z * sp [14 + 4*f];
                pb += x.y * sp [13 + 4*f] + x.w * sp [15 + 4*f];
                ga += x.x * spg[12 + 4*f] + x.z * spg[14 + 4*f];
                gb += x.y * spg[13 + 4*f] + x.w * spg[15 + 4*f];
            }
            float4 t = Sr[12];           // x=col48, y=col49, z=u, w=pad
            pa += t.x * sp [60] + t.z;   pb += t.y * sp [61];
            ga += t.x * spg[60] + t.z;   gb += t.y * spg[61];
            float s = pa + pb, g = ga + gb;
            bv[l] = s; bvg[l] = g;
            if (l < 204) {
                float s2 = s * s;
                int c3 = l % 3;
                if (c3 == 0) tn0 += s2; else if (c3 == 1) tn1 += s2; else tn2 += s2;
            }
        } else {
            // pred-only (ridx_w rows) -> tn
            float pa = 0.f, pb = 0.f;
#pragma unroll
            for (int f = 0; f < 12; f++) {
                float4 x = Sr[f];
                pa += x.x * sp[12 + 4*f] + x.z * sp[14 + 4*f];
                pb += x.y * sp[13 + 4*f] + x.w * sp[15 + 4*f];
            }
            float4 t = Sr[12];
            pa += t.x * sp[60] + t.z;
            pb += t.y * sp[61];
            float s = pa + pb;
            float s2 = s * s;
            int c3 = l % 3;
            if (c3 == 0) tn0 += s2; else if (c3 == 1) tn1 += s2; else tn2 += s2;
        }
    }
    tn0 = warp_sum(tn0); tn1 = warp_sum(tn1); tn2 = warp_sum(tn2);
    if (lane == 0) { tn_w[wid][0] = tn0; tn_w[wid][1] = tn1; tn_w[wid][2] = tn2; }
    __syncthreads();

    // ---- 3. fold tn, rotate verts (+|v|^2 in .w), wait for wcol flag ----
    if (tid < 3) {
        float s = 0.f;
#pragma unroll
        for (int w = 0; w < 16; w++) s += tn_w[w][tid];
        tnsq[tid] = s;
    }
    if (tid >= 256 && tid < 456) {
        int t = tid - 256;
        float b0 = bv [3*t], b1 = bv [3*t+1], b2 = bv [3*t+2];
        float c0 = bvg[3*t], c1 = bvg[3*t+1], c2 = bvg[3*t+2];
        float4 o1, o2;
        o1.x = sp [0]*b0 + sp [1]*b1 + sp [2]*b2 + sp [3];
        o1.y = sp [4]*b0 + sp [5]*b1 + sp [6]*b2 + sp [7];
        o1.z = sp [8]*b0 + sp [9]*b1 + sp[10]*b2 + sp[11];
        o1.w = o1.x*o1.x + o1.y*o1.y + o1.z*o1.z;
        o2.x = spg[0]*c0 + spg[1]*c1 + spg[2]*c2 + spg[3];
        o2.y = spg[4]*c0 + spg[5]*c1 + spg[6]*c2 + spg[7];
        o2.z = spg[8]*c0 + spg[9]*c1 + spg[10]*c2 + spg[11];
        o2.w = o2.x*o2.x + o2.y*o2.y + o2.z*o2.z;
        vt4[t] = o1; vtg4[t] = o2;
    }
    if (tid == 32) {
        while (atomicAdd(&g_wflag, 0) == 0) __nanosleep(64);
    }
    __syncthreads();
    __threadfence();  // acquire for g_wcol

    // ---- 4. warp0: weights+wpdc; chamfer tid 96..195 & 256..355; warp 15: nwl ----
    float tot = 0.f;
    if (wid == 0) {
        int p1 = lane, p2 = lane + 32;
        float wj1, wj2 = 0.f;
        {
            float pd = fabsf(sp[p1] - spg[p1]);
            if (p1 < 11) {
                int cc = p1 & 3;
                float sc = (cc < 3) ? sqrtf(tnsq[cc]) : 14.142135623730951f;
                wj1 = pd * sc + 1e-6f;
            } else if (p1 == 11) wj1 = 1e-6f;
            else wj1 = 0.00057339936f * pd * g_wcol[p1 - 12] + 1e-6f;
        }
        if (p2 < 62) {
            float pd = fabsf(sp[p2] - spg[p2]);
            wj2 = 0.00057339936f * pd * g_wcol[p2 - 12] + 1e-6f;
        }
        float m = fmaxf(wj1, wj2);
#pragma unroll
        for (int o = 16; o; o >>= 1) m = fmaxf(m, __shfl_xor_sync(0xffffffffu, m, o));
        float wpdc = 0.f;
        if (p1 != 11) {
            float d = input[n * 62 + p1] - target[n * 62 + p1];
            wpdc += (wj1 / m) * d * d;
        }
        if (p2 < 62) {
            float d = input[n * 62 + p2] - target[n * 62 + p2];
            wpdc += (wj2 / m) * d * d;
        }
        tot += wpdc * (1.f / (128.f * 62.f));
    } else if (tid >= 96 && tid < 196) {
        int t = tid - 96;
        float4 X1 = vtg4[t], X2 = vtg4[t + 100];
        float x1x = -2.f*X1.x, x1y = -2.f*X1.y, x1z = -2.f*X1.z;
        float x2x = -2.f*X2.x, x2y = -2.f*X2.y, x2z = -2.f*X2.z;
        float m1a = 3.4e38f, m1b = 3.4e38f, m2a = 3.4e38f, m2b = 3.4e38f;
#pragma unroll 4
        for (int k = 0; k < 200; k += 2) {
            float4 a = vt4[k], b = vt4[k + 1];
            m1a = fminf(m1a, fmaf(x1x, a.x, fmaf(x1y, a.y, fmaf(x1z, a.z, a.w))));
            m1b = fminf(m1b, fmaf(x1x, b.x, fmaf(x1y, b.y, fmaf(x1z, b.z, b.w))));
            m2a = fminf(m2a, fmaf(x2x, a.x, fmaf(x2y, a.y, fmaf(x2z, a.z, a.w))));
            m2b = fminf(m2b, fmaf(x2x, b.x, fmaf(x2y, b.y, fmaf(x2z, b.z, b.w))));
        }
        float d1 = X1.w + fminf(m1a, m1b);
        float d2 = X2.w + fminf(m2a, m2b);
        tot += (d1 + d2) * (3.f * 0.001f / (128.f * 200.f));
    } else if (tid >= 256 && tid < 356) {
        int t = tid - 256;
        float4 Y1 = vt4[t], Y2 = vt4[t + 100];
        float y1x = -2.f*Y1.x, y1y = -2.f*Y1.y, y1z = -2.f*Y1.z;
        float y2x = -2.f*Y2.x, y2y = -2.f*Y2.y, y2z = -2.f*Y2.z;
        float m1a = 3.4e38f, m1b = 3.4e38f, m2a = 3.4e38f, m2b = 3.4e38f;
#pragma unroll 4
        for (int k = 0; k < 200; k += 2) {
            float4 a = vtg4[k], b = vtg4[k + 1];
            m1a = fminf(m1a, fmaf(y1x, a.x, fmaf(y1y, a.y, fmaf(y1z, a.z, a.w))));
            m1b = fminf(m1b, fmaf(y1x, b.x, fmaf(y1y, b.y, fmaf(y1z, b.z, b.w))));
            m2a = fminf(m2a, fmaf(y2x, a.x, fmaf(y2y, a.y, fmaf(y2z, a.z, a.w))));
            m2b = fminf(m2b, fmaf(y2x, b.x, fmaf(y2y, b.y, fmaf(y2z, b.z, b.w))));
        }
        float d1 = Y1.w + fminf(m1a, m1b);
        float d2 = Y2.w + fminf(m2a, m2b);
        tot += (d1 + d2) * (3.f * 0.001f / (128.f * 200.f));
    } else if (wid == 15) {
        const float k_nwl = 3.f * 0.001f / (128.f * 68.f * 3.f);
        {
            int t = lane;
            float d0 = vtg4[t].x - vt4[t].x;
            float d1 = vtg4[t].y - vt4[t].y;
            float d2 = vtg4[t].z - vt4[t].z;
            tot += ns0 * (d0*d0 + d1*d1 + d2*d2) * k_nwl;
        }
        {
            int t = lane + 32;
            float d0 = vtg4[t].x - vt4[t].x;
            float d1 = vtg4[t].y - vt4[t].y;
            float d2 = vtg4[t].z - vt4[t].z;
            tot += ns1 * (d0*d0 + d1*d1 + d2*d2) * k_nwl;
        }
        if (lane < 4) {
            int t = lane + 64;
            float d0 = vtg4[t].x - vt4[t].x;
            float d1 = vtg4[t].y - vt4[t].y;
            float d2 = vtg4[t].z - vt4[t].z;
            tot += ns2 * (d0*d0 + d1*d1 + d2*d2) * k_nwl;
        }
    }

    // ---- 5. block reduce + finalize (fixed order -> deterministic) ----
    tot = warp_sum(tot);
    if (lane == 0) wsum[wid] = tot;
    __syncthreads();
    if (tid == 0) {
        float b = 0.f;
#pragma unroll
        for (int w = 0; w < 16; w++) b += wsum[w];
        g_partials[n] = b;
        __threadfence();
        unsigned int old = atomicAdd(&g_count, 1u);
        s_last = (old == BATCH - 1);
    }
    __syncthreads();
    if (s_last) {
        __threadfence();
        if (wid == 0) {
            float v = g_partials[lane] + g_partials[lane + 32]
                    + g_partials[lane + 64] + g_partials[lane + 96];
#pragma unroll
            for (int o = 16; o; o >>= 1) v += __shfl_down_sync(0xffffffffu, v, o);
            if (lane == 0) { out[0] = v; g_count = 0; g_wflag = 0; }
        }
    }
}

extern "C" void kernel_launch(void* const* d_in, const int* in_sizes, int n_in,
                              void* d_out, int out_size)
{
    (void)in_sizes; (void)n_in; (void)out_size;
    cudaFuncSetAttribute(loss_main, cudaFuncAttributeMaxDynamicSharedMemorySize, S_BYTES);
    loss_main<<<BATCH + 1, NT, S_BYTES>>>(
        (const float*)d_in[0],   // input
        (const float*)d_in[1],   // target
        (const float*)d_in[2],   // normals
        (const float*)d_in[3],   // param_mean
        (const float*)d_in[4],   // param_std
        (const float*)d_in[5],   // u
        (const float*)d_in[6],   // w_shp
        (const float*)d_in[7],   // w_exp
        (const int*)d_in[8],     // keyindex
        (const int*)d_in[9],     // resample_idx_w
        (const int*)d_in[10],    // resample_idx_v
        (float*)d_out);
}